// round 1
// baseline (speedup 1.0000x reference)
#include <cuda_runtime.h>

#define S_LEN 512
#define BATCH 64
#define IDIM  512
#define HDIM  512
#define NB    128     // persistent blocks (<=148 SMs, 1 wave guaranteed)
#define HC    4       // hidden cols per block: NB*HC = HDIM
#define CHUNK 128     // K-chunk of h_prev staged in smem
#define HPAD  132     // padded row stride for h chunk (conflict-free)

// Scratch: gx[s][g][b][h]  (256 MB) — sanctioned __device__ global scratch
__device__ float g_gx[(size_t)S_LEN * 4 * BATCH * HDIM];

// Software grid barrier state (gen is monotonically increasing across launches;
// count always returns to 0 at the end of each barrier -> launch-safe)
__device__ unsigned g_bar_count = 0;
__device__ unsigned g_bar_gen   = 0;

__device__ __forceinline__ void grid_barrier() {
    __syncthreads();
    if (threadIdx.x == 0) {
        volatile unsigned* gen = &g_bar_gen;
        unsigned my = *gen;
        __threadfence();  // release: make this block's h-writes visible before arrival
        unsigned arrived = atomicAdd(&g_bar_count, 1u);
        if (arrived == gridDim.x - 1) {
            atomicExch(&g_bar_count, 0u);
            __threadfence();
            atomicAdd(&g_bar_gen, 1u);   // release all
        } else {
            while (*gen == my) { /* spin on L2 */ }
        }
        __threadfence();  // acquire side
    }
    __syncthreads();
}

// ---------------------------------------------------------------------------
// K1: gx[s][g][b][h] = x[s,b,:] @ W_g + b_g     (M=32768, N=2048, K=512)
// 128x64 tile, BK=16, 256 threads, 8x4 microtile
// ---------------------------------------------------------------------------
__global__ __launch_bounds__(256) void gemm_gx(
    const float* __restrict__ x,
    const float* __restrict__ W0, const float* __restrict__ W1,
    const float* __restrict__ W2, const float* __restrict__ W3,
    const float* __restrict__ b0, const float* __restrict__ b1,
    const float* __restrict__ b2, const float* __restrict__ b3)
{
    __shared__ float As[16][132];   // [k][m], padded
    __shared__ float Bs[16][68];    // [k][n], padded

    const int m0 = blockIdx.x * 128;
    const int nt = blockIdx.y;            // 0..31 (tiles of 64 along N=2048)
    const int g  = nt >> 3;               // 8 tiles per gate
    const int h0 = (nt & 7) * 64;

    const float* W    = (g == 0) ? W0 : (g == 1) ? W1 : (g == 2) ? W2 : W3;
    const float* bias = (g == 0) ? b0 : (g == 1) ? b1 : (g == 2) ? b2 : b3;

    const int tid = threadIdx.x;
    const int tx = tid & 15;              // n-dim
    const int ty = tid >> 4;              // m-dim

    float acc[8][4];
#pragma unroll
    for (int i = 0; i < 8; i++)
#pragma unroll
        for (int j = 0; j < 4; j++) acc[i][j] = 0.f;

    for (int k0 = 0; k0 < IDIM; k0 += 16) {
        // A tile: 128 x 16 (transpose into As[k][m])
#pragma unroll
        for (int i = 0; i < 2; i++) {
            int idx = tid + 256 * i;          // 0..511
            int r   = idx >> 2;               // 0..127
            int c4  = idx & 3;                // 0..3
            float4 v = *(const float4*)&x[(size_t)(m0 + r) * IDIM + k0 + c4 * 4];
            As[c4 * 4 + 0][r] = v.x;
            As[c4 * 4 + 1][r] = v.y;
            As[c4 * 4 + 2][r] = v.z;
            As[c4 * 4 + 3][r] = v.w;
        }
        // B tile: 16 x 64
        {
            int r  = tid >> 4;                // 0..15
            int c4 = tid & 15;                // 0..15
            float4 v = *(const float4*)&W[(size_t)(k0 + r) * HDIM + h0 + c4 * 4];
            *(float4*)&Bs[r][c4 * 4] = v;
        }
        __syncthreads();

#pragma unroll
        for (int k = 0; k < 16; k++) {
            float a[8], bq[4];
#pragma unroll
            for (int i = 0; i < 8; i++) a[i] = As[k][ty * 8 + i];
#pragma unroll
            for (int j = 0; j < 4; j++) bq[j] = Bs[k][tx * 4 + j];
#pragma unroll
            for (int i = 0; i < 8; i++)
#pragma unroll
                for (int j = 0; j < 4; j++) acc[i][j] += a[i] * bq[j];
        }
        __syncthreads();
    }

    // Epilogue: + bias, scatter into gx[s][g][b][h]
#pragma unroll
    for (int i = 0; i < 8; i++) {
        int m  = m0 + ty * 8 + i;
        int s  = m >> 6;
        int bb = m & 63;
        size_t base = (((size_t)s * 4 + g) * BATCH + bb) * HDIM + h0;
#pragma unroll
        for (int j = 0; j < 4; j++) {
            int n = tx * 4 + j;
            g_gx[base + n] = acc[i][j] + bias[h0 + n];
        }
    }
}

// ---------------------------------------------------------------------------
// K2: persistent recurrent kernel.
// 128 blocks x 256 threads; block owns HC=4 hidden columns, thread owns one
// (batch b, column c) cell; c-state in register; h written to out[t] directly.
// dyn smem: Us[4][HC][512] (32KB, persists all steps) + hsm[64][HPAD] (33KB)
// ---------------------------------------------------------------------------
__global__ __launch_bounds__(256) void lstm_rec(
    const float* __restrict__ U0, const float* __restrict__ U1,
    const float* __restrict__ U2, const float* __restrict__ U3,
    float* __restrict__ out)
{
    extern __shared__ float smem[];
    float* Us  = smem;                    // 4*HC*512 floats
    float* hsm = smem + 4 * HC * 512;     // 64*HPAD floats

    const int tid  = threadIdx.x;
    const int c    = tid >> 6;            // 0..3 (column within block)
    const int b    = tid & 63;            // 0..63 (batch)
    const int col0 = blockIdx.x * HC;

    // One-time load of the U slice (columns col0..col0+3, all 4 gates, all k)
    {
        const float* Uptr[4] = {U0, U1, U2, U3};
        for (int i = tid; i < 4 * HC * 512; i += 256) {
            int gg = i & 3;
            int cc = (i >> 2) & 3;
            int k  = i >> 4;
            Us[(gg * HC + cc) * 512 + k] = Uptr[gg][(size_t)k * HDIM + col0 + cc];
        }
    }
    __syncthreads();

    const float* Ui = &Us[(0 * HC + c) * 512];
    const float* Uf = &Us[(1 * HC + c) * 512];
    const float* Uo = &Us[(2 * HC + c) * 512];
    const float* Uc = &Us[(3 * HC + c) * 512];

    float cstate = 0.f;
    float hval   = 0.f;

    for (int t = 0; t < S_LEN; t++) {
        size_t gbase = (((size_t)t * 4) * BATCH + b) * HDIM + col0 + c;
        float aI = g_gx[gbase];
        float aF = g_gx[gbase + 1 * (size_t)BATCH * HDIM];
        float aO = g_gx[gbase + 2 * (size_t)BATCH * HDIM];
        float aC = g_gx[gbase + 3 * (size_t)BATCH * HDIM];

        if (t > 0) {
            const float* hprev = out + (size_t)(t - 1) * BATCH * HDIM;
            for (int kc = 0; kc < HDIM; kc += CHUNK) {
                // Cooperative load of h_prev[0:64][kc:kc+CHUNK] (coalesced float4)
#pragma unroll
                for (int i = 0; i < 8; i++) {           // 2048 float4 / 256 thr
                    int idx = tid + 256 * i;
                    int r   = idx >> 5;                 // 0..63
                    int c4  = idx & 31;                 // 0..31
                    float4 v = *(const float4*)&hprev[(size_t)r * HDIM + kc + c4 * 4];
                    *(float4*)&hsm[r * HPAD + c4 * 4] = v;
                }
                __syncthreads();
#pragma unroll 4
                for (int k4 = 0; k4 < CHUNK / 4; k4++) {
                    float4 hv = *(const float4*)&hsm[b * HPAD + k4 * 4];
                    int kk = kc + k4 * 4;
                    float4 u;
                    u = *(const float4*)&Ui[kk];
                    aI += hv.x * u.x + hv.y * u.y + hv.z * u.z + hv.w * u.w;
                    u = *(const float4*)&Uf[kk];
                    aF += hv.x * u.x + hv.y * u.y + hv.z * u.z + hv.w * u.w;
                    u = *(const float4*)&Uo[kk];
                    aO += hv.x * u.x + hv.y * u.y + hv.z * u.z + hv.w * u.w;
                    u = *(const float4*)&Uc[kk];
                    aC += hv.x * u.x + hv.y * u.y + hv.z * u.z + hv.w * u.w;
                }
                __syncthreads();
            }
        }

        float ig = 1.f / (1.f + expf(-aI));
        float fg = 1.f / (1.f + expf(-aF));
        float og = 1.f / (1.f + expf(-aO));
        float ct = tanhf(aC);
        cstate = fg * cstate + ig * ct;
        hval   = og * tanhf(cstate);

        out[(size_t)t * BATCH * HDIM + (size_t)b * HDIM + col0 + c] = hval;
        grid_barrier();   // includes release fence for the h write above
    }

    // h_fin = hs[last]  (each thread still holds its h in a register)
    out[(size_t)S_LEN * BATCH * HDIM + (size_t)b * HDIM + col0 + c] = hval;
    // c0 output is zeros (reference reproduces the "return initial c" bug)
    out[(size_t)S_LEN * BATCH * HDIM + (size_t)BATCH * HDIM
        + (size_t)blockIdx.x * 256 + tid] = 0.f;
}

// ---------------------------------------------------------------------------
extern "C" void kernel_launch(void* const* d_in, const int* in_sizes, int n_in,
                              void* d_out, int out_size)
{
    const float* x  = (const float*)d_in[0];
    const float* W0 = (const float*)d_in[1];
    const float* W1 = (const float*)d_in[2];
    const float* W2 = (const float*)d_in[3];
    const float* W3 = (const float*)d_in[4];
    const float* U0 = (const float*)d_in[5];
    const float* U1 = (const float*)d_in[6];
    const float* U2 = (const float*)d_in[7];
    const float* U3 = (const float*)d_in[8];
    const float* b0 = (const float*)d_in[9];
    const float* b1 = (const float*)d_in[10];
    const float* b2 = (const float*)d_in[11];
    const float* b3 = (const float*)d_in[12];
    float* out = (float*)d_out;

    const int smem_bytes = (4 * HC * 512 + 64 * HPAD) * sizeof(float);  // 66560
    cudaFuncSetAttribute(lstm_rec, cudaFuncAttributeMaxDynamicSharedMemorySize,
                         smem_bytes);

    dim3 g1(32768 / 128, 2048 / 64);   // (256, 32)
    gemm_gx<<<g1, 256>>>(x, W0, W1, W2, W3, b0, b1, b2, b3);
    lstm_rec<<<NB, 256, smem_bytes>>>(U0, U1, U2, U3, out);
}

// round 3
// speedup vs baseline: 2.6295x; 2.6295x over previous
#include <cuda_runtime.h>
#include <cuda_fp16.h>
#include <cstdint>

#define S_LEN 512
#define BATCH 64
#define IDIM  512
#define HDIM  512

// ---------------- scratch (device globals; allocation-free) ----------------
__device__ float  g_gx[(size_t)S_LEN * 4 * HDIM * BATCH];   // [t][g][h][b] fp32
__device__ __half g_xh[(size_t)S_LEN * BATCH * IDIM];       // [m][k] fp16
__device__ __half g_Wp[(size_t)4 * HDIM * IDIM];            // [n=g*512+h][k] fp16
__device__ __half g_Up[(size_t)4 * HDIM * HDIM];            // [n2=cta*16+g*4+cc][k] fp16
__device__ float  g_bp[4 * HDIM];                           // packed bias [n]
__device__ __half g_hh[2][BATCH * HDIM];                    // double-buffered h, fp16

__device__ unsigned g_bar_count = 0;
__device__ unsigned g_bar_gen   = 0;

// ---------------- helpers ----------------
static __device__ __forceinline__ uint32_t smem_u32(const void* p) {
    uint32_t a;
    asm("{ .reg .u64 t; cvta.to.shared.u64 t, %1; cvt.u32.u64 %0, t; }" : "=r"(a) : "l"(p));
    return a;
}
static __device__ __forceinline__ void ldsm4(uint32_t* r, uint32_t a) {
    asm volatile("ldmatrix.sync.aligned.m8n8.x4.shared.b16 {%0,%1,%2,%3}, [%4];"
                 : "=r"(r[0]), "=r"(r[1]), "=r"(r[2]), "=r"(r[3]) : "r"(a));
}
static __device__ __forceinline__ void mma16816(float* d, const uint32_t* a, const uint32_t* b) {
    asm volatile("mma.sync.aligned.m16n8k16.row.col.f32.f16.f16.f32 "
                 "{%0,%1,%2,%3}, {%4,%5,%6,%7}, {%8,%9}, {%0,%1,%2,%3};"
                 : "+f"(d[0]), "+f"(d[1]), "+f"(d[2]), "+f"(d[3])
                 : "r"(a[0]), "r"(a[1]), "r"(a[2]), "r"(a[3]), "r"(b[0]), "r"(b[1]));
}
__device__ __forceinline__ float sigf(float x)    { return __fdividef(1.f, 1.f + __expf(-x)); }
__device__ __forceinline__ float tanhf_e(float x) { return __fdividef(2.f, 1.f + __expf(-2.f * x)) - 1.f; }

__device__ __forceinline__ void grid_barrier() {
    __syncthreads();
    if (threadIdx.x == 0) {
        volatile unsigned* gen = &g_bar_gen;
        unsigned my = *gen;
        __threadfence();   // release: h writes visible before arrival
        unsigned arrived = atomicAdd(&g_bar_count, 1u);
        if (arrived == gridDim.x - 1) {
            atomicExch(&g_bar_count, 0u);
            __threadfence();
            atomicAdd(&g_bar_gen, 1u);
        } else {
            while (*gen == my) { }
        }
        __threadfence();
    }
    __syncthreads();
}

// ---------------- pack kernels ----------------
__global__ void conv_x(const float* __restrict__ x) {
    size_t i = (size_t)blockIdx.x * 256 + threadIdx.x;     // float4 index
    float4 v = ((const float4*)x)[i];
    __half2 a = __floats2half2_rn(v.x, v.y);
    __half2 b = __floats2half2_rn(v.z, v.w);
    uint2 u;
    u.x = *reinterpret_cast<uint32_t*>(&a);
    u.y = *reinterpret_cast<uint32_t*>(&b);
    ((uint2*)g_xh)[i] = u;
}
__global__ void pack_W(const float* __restrict__ W0, const float* __restrict__ W1,
                       const float* __restrict__ W2, const float* __restrict__ W3) {
    int n = blockIdx.x;                 // 0..2047 = g*512+h
    int g = n >> 9, h = n & 511;
    const float* Wg = (g == 0) ? W0 : (g == 1) ? W1 : (g == 2) ? W2 : W3;
    for (int k = threadIdx.x; k < IDIM; k += 256)
        g_Wp[(size_t)n * IDIM + k] = __float2half(Wg[(size_t)k * HDIM + h]);
}
__global__ void pack_U(const float* __restrict__ U0, const float* __restrict__ U1,
                       const float* __restrict__ U2, const float* __restrict__ U3) {
    int n2 = blockIdx.x;                // 0..2047 = cta*16 + g*4 + cc
    int cta = n2 >> 4, j = n2 & 15;
    int g = j >> 2, cc = j & 3;
    int col = cta * 4 + cc;
    const float* Ug = (g == 0) ? U0 : (g == 1) ? U1 : (g == 2) ? U2 : U3;
    for (int k = threadIdx.x; k < HDIM; k += 256)
        g_Up[(size_t)n2 * HDIM + k] = __float2half(Ug[(size_t)k * HDIM + col]);
}
__global__ void pack_b(const float* __restrict__ b0, const float* __restrict__ b1,
                       const float* __restrict__ b2, const float* __restrict__ b3) {
    for (int n = threadIdx.x; n < 4 * HDIM; n += 256) {
        int g = n >> 9, h = n & 511;
        g_bp[n] = (g == 0) ? b0[h] : (g == 1) ? b1[h] : (g == 2) ? b2[h] : b3[h];
    }
}

// ---------------- K1: gx = x @ W + b  (HMMA, full-K staging) ----------------
#define APITCH 520                       // halfs per smem row (pad 8)
#define K1_SMEM ((128 * APITCH + 64 * APITCH) * 2)   // 199680 B

__global__ __launch_bounds__(256) void gemm_gx() {
    extern __shared__ char smem[];
    __half* As  = (__half*)smem;                 // [128][520]
    __half* Bs  = As + 128 * APITCH;             // [64][520]
    float*  Dsm = (float*)smem;                  // [128][66], reused after mma

    const int tid = threadIdx.x, lane = tid & 31, wid = tid >> 5;
    const int m0 = blockIdx.x * 128, n0 = blockIdx.y * 64;

    for (int i = tid; i < 128 * 64; i += 256) {
        int r = i >> 6, q = i & 63;
        *(uint4*)(As + r * APITCH + q * 8) =
            *(const uint4*)(g_xh + (size_t)(m0 + r) * IDIM + q * 8);
    }
    for (int i = tid; i < 64 * 64; i += 256) {
        int r = i >> 6, q = i & 63;
        *(uint4*)(Bs + r * APITCH + q * 8) =
            *(const uint4*)(g_Wp + (size_t)(n0 + r) * IDIM + q * 8);
    }
    __syncthreads();

    const int wm = wid & 3, wn = wid >> 2;       // warp tile: rows wm*32, cols wn*32
    float acc[2][4][4];
#pragma unroll
    for (int i = 0; i < 2; i++)
#pragma unroll
        for (int j = 0; j < 4; j++)
#pragma unroll
            for (int k = 0; k < 4; k++) acc[i][j][k] = 0.f;

    const uint32_t a_base = smem_u32(As), b_base = smem_u32(Bs);
#pragma unroll 4
    for (int ks = 0; ks < 32; ks++) {
        uint32_t af[2][4];
#pragma unroll
        for (int mt = 0; mt < 2; mt++) {
            int row = wm * 32 + mt * 16 + (lane & 15);
            int col = ks * 16 + ((lane >> 4) << 3);
            ldsm4(af[mt], a_base + (row * APITCH + col) * 2);
        }
        uint32_t bf[2][4];
#pragma unroll
        for (int bp = 0; bp < 2; bp++) {
            int row = wn * 32 + bp * 16 + ((lane >> 4) << 3) + (lane & 7);
            int col = ks * 16 + (((lane >> 3) & 1) << 3);
            ldsm4(bf[bp], b_base + (row * APITCH + col) * 2);
        }
#pragma unroll
        for (int mt = 0; mt < 2; mt++)
#pragma unroll
            for (int nt = 0; nt < 4; nt++)
                mma16816(acc[mt][nt], af[mt], &bf[nt >> 1][(nt & 1) * 2]);
    }
    __syncthreads();

    // accs -> Dsm [128][66]
#pragma unroll
    for (int mt = 0; mt < 2; mt++)
#pragma unroll
        for (int nt = 0; nt < 4; nt++) {
            int r0 = wm * 32 + mt * 16 + lane / 4;
            int c0 = wn * 32 + nt * 8 + (lane % 4) * 2;
            Dsm[r0 * 66 + c0]       = acc[mt][nt][0];
            Dsm[r0 * 66 + c0 + 1]   = acc[mt][nt][1];
            Dsm[(r0 + 8) * 66 + c0]     = acc[mt][nt][2];
            Dsm[(r0 + 8) * 66 + c0 + 1] = acc[mt][nt][3];
        }
    __syncthreads();

    // coalesced writeback: gx[t][g][h][b], + bias
    const int s0 = m0 >> 6;          // two s values per CTA
    const int g = n0 >> 9, h0 = n0 & 511;
    for (int idx = tid; idx < 2048; idx += 256) {
        int n = idx >> 5, rem = idx & 31, sl = rem >> 4, bq = rem & 15;
        float bias = g_bp[n0 + n];
        int mbase = sl * 64 + bq * 4;
        float4 v;
        v.x = Dsm[(mbase + 0) * 66 + n] + bias;
        v.y = Dsm[(mbase + 1) * 66 + n] + bias;
        v.z = Dsm[(mbase + 2) * 66 + n] + bias;
        v.w = Dsm[(mbase + 3) * 66 + n] + bias;
        size_t o = (((size_t)((s0 + sl) * 4 + g)) * 512 + h0 + n) * 64 + bq * 4;
        *(float4*)(g_gx + o) = v;
    }
}

// ---------------- K2: persistent HMMA recurrence ----------------
// 128 CTAs x 256 thr; CTA owns 4 hidden cols x 4 gates (N=16); U fragments
// live in registers for all 512 steps; h broadcast via fp16 g_hh double buffer.
#define HPITCH 520
#define K2_SMEM (64 * HPITCH * 2 + 64 * 18 * 4)   // 71168 B

__global__ __launch_bounds__(256) void lstm_rec(float* __restrict__ out) {
    extern __shared__ char smem[];
    __half* hsm = (__half*)smem;                   // [64][520]
    float*  Dsm = (float*)(smem + 64 * HPITCH * 2);  // [64][18]

    const int tid = threadIdx.x, lane = tid & 31, wid = tid >> 5;
    const int cta = blockIdx.x, col0 = cta * 4;
    const int wm = wid & 3, wn = wid >> 2;         // m rows wm*16.., n j=wn*8..

    // persistent B fragments: thread holds U^T[n][k] pairs in mma layout
    uint32_t Bf[32][2];
    {
        const __half* Up = g_Up + (size_t)(cta * 16 + wn * 8 + lane / 4) * HDIM;
        const int kk = (lane % 4) * 2;
#pragma unroll
        for (int ks = 0; ks < 32; ks++) {
            Bf[ks][0] = *(const uint32_t*)(Up + ks * 16 + kk);
            Bf[ks][1] = *(const uint32_t*)(Up + ks * 16 + kk + 8);
        }
    }

    const int b_ep = tid >> 2, cc = tid & 3;       // epilogue cell (b, col)
    float cs = 0.f;
    const uint32_t h_base = smem_u32(hsm);

    for (int t = 0; t < S_LEN; t++) {
        float acc[4] = {0.f, 0.f, 0.f, 0.f};
        if (t > 0) {
            const __half* hp = g_hh[(t - 1) & 1];
            for (int i = tid; i < 64 * 64; i += 256) {
                int r = i >> 6, q = i & 63;
                *(uint4*)(hsm + r * HPITCH + q * 8) =
                    *(const uint4*)(hp + (size_t)r * HDIM + q * 8);
            }
            __syncthreads();
#pragma unroll
            for (int ks = 0; ks < 32; ks++) {
                uint32_t af[4];
                int row = wm * 16 + (lane & 15);
                int col = ks * 16 + ((lane >> 4) << 3);
                ldsm4(af, h_base + (row * HPITCH + col) * 2);
                mma16816(acc, af, Bf[ks]);
            }
        }

        // gx prefetch (coalesced: 8 consecutive b per cc-group)
        float gxr[4];
#pragma unroll
        for (int g = 0; g < 4; g++)
            gxr[g] = g_gx[(((size_t)t * 4 + g) * 512 + col0 + cc) * 64 + b_ep];

        if (t > 0) {
            int r0 = wm * 16 + lane / 4, c0 = wn * 8 + (lane % 4) * 2;
            Dsm[r0 * 18 + c0]           = acc[0];
            Dsm[r0 * 18 + c0 + 1]       = acc[1];
            Dsm[(r0 + 8) * 18 + c0]     = acc[2];
            Dsm[(r0 + 8) * 18 + c0 + 1] = acc[3];
        }
        __syncthreads();

        float dI = 0.f, dF = 0.f, dO = 0.f, dC = 0.f;
        if (t > 0) {
            dI = Dsm[b_ep * 18 + 0 + cc];
            dF = Dsm[b_ep * 18 + 4 + cc];
            dO = Dsm[b_ep * 18 + 8 + cc];
            dC = Dsm[b_ep * 18 + 12 + cc];
        }
        float ig = sigf(dI + gxr[0]);
        float fg = sigf(dF + gxr[1]);
        float og = sigf(dO + gxr[2]);
        float ct = tanhf_e(dC + gxr[3]);
        cs = fg * cs + ig * ct;
        float h = og * tanhf_e(cs);

        out[(size_t)t * BATCH * HDIM + (size_t)b_ep * HDIM + col0 + cc] = h;
        g_hh[t & 1][b_ep * HDIM + col0 + cc] = __float2half(h);
        if (t == S_LEN - 1)
            out[(size_t)S_LEN * BATCH * HDIM + (size_t)b_ep * HDIM + col0 + cc] = h;

        grid_barrier();   // publishes h(t); also fences Dsm/hsm reuse
    }

    // c0 output region = zeros (reference returns the INITIAL c)
    {
        float* c0p = out + (size_t)(S_LEN + 1) * BATCH * HDIM;
        int i = blockIdx.x * 256 + tid;
        if (i < BATCH * HDIM) c0p[i] = 0.f;
    }
}

// ---------------- launcher ----------------
extern "C" void kernel_launch(void* const* d_in, const int* in_sizes, int n_in,
                              void* d_out, int out_size)
{
    const float* x  = (const float*)d_in[0];
    const float* W0 = (const float*)d_in[1];
    const float* W1 = (const float*)d_in[2];
    const float* W2 = (const float*)d_in[3];
    const float* W3 = (const float*)d_in[4];
    const float* U0 = (const float*)d_in[5];
    const float* U1 = (const float*)d_in[6];
    const float* U2 = (const float*)d_in[7];
    const float* U3 = (const float*)d_in[8];
    const float* b0 = (const float*)d_in[9];
    const float* b1 = (const float*)d_in[10];
    const float* b2 = (const float*)d_in[11];
    const float* b3 = (const float*)d_in[12];
    float* out = (float*)d_out;

    cudaFuncSetAttribute(gemm_gx, cudaFuncAttributeMaxDynamicSharedMemorySize, K1_SMEM);
    cudaFuncSetAttribute(lstm_rec, cudaFuncAttributeMaxDynamicSharedMemorySize, K2_SMEM);

    conv_x<<<(S_LEN * BATCH * IDIM / 4) / 256, 256>>>(x);
    pack_W<<<4 * HDIM, 256>>>(W0, W1, W2, W3);
    pack_U<<<4 * HDIM, 256>>>(U0, U1, U2, U3);
    pack_b<<<1, 256>>>(b0, b1, b2, b3);

    dim3 g1(256, 32);
    gemm_gx<<<g1, 256, K1_SMEM>>>();
    lstm_rec<<<128, 256, K2_SMEM>>>(out);
}